// round 3
// baseline (speedup 1.0000x reference)
#include <cuda_runtime.h>

// SVD_9990093931239 — batched Kabsch alignment, algebraically collapsed.
//   tt = src + pose -> tt_c == src_c -> H = src_c @ src_c^T (symmetric PSD)
//   => U == V => R = I, det=+1 (no reflection branch), t = pose.
// Output: [B*9 floats of R][B*3 floats of t]. B=4096 -> 49152 floats = 192KB.
//
// R3: launch-ramp-bound regime. Hoist the pose LDG above the branch
// (clamped index) so DRAM latency overlaps the ramp instead of serializing
// the tail; identity pattern via bitmask 0x111 (bits 0,4,8 set).

__global__ void svd_identity_pose_v4(const float4* __restrict__ pose4,
                                     float4* __restrict__ out4,
                                     int r_q,     // B*9/4 float4s in R section
                                     int total_q) // out_size/4
{
    int q = blockIdx.x * blockDim.x + threadIdx.x;
    if (q >= total_q) return;

    // Unconditional load, clamped so R-section threads read element 0 harmlessly.
    int pidx = q - r_q;
    float4 pv = pose4[pidx < 0 ? 0 : pidx];

    if (q < r_q) {
        int p = (q * 4) % 9;                       // position in 9-float pattern
        float4 v;
        v.x = (float)((0x111u >> p) & 1u); p = (p == 8) ? 0 : p + 1;
        v.y = (float)((0x111u >> p) & 1u); p = (p == 8) ? 0 : p + 1;
        v.z = (float)((0x111u >> p) & 1u); p = (p == 8) ? 0 : p + 1;
        v.w = (float)((0x111u >> p) & 1u);
        out4[q] = v;
    } else {
        out4[q] = pv;                              // t[b,:] = pose[b,:,0]
    }
}

extern "C" void kernel_launch(void* const* d_in, const int* in_sizes, int n_in,
                              void* d_out, int out_size)
{
    // inputs: [0]=source [B,N,3], [1]=template [B,N,3], [2]=pose [B,3,1]
    const float4* pose4 = (const float4*)d_in[2];
    float4* out4 = (float4*)d_out;

    const int B = in_sizes[2] / 3;          // 4096
    const int r_q = (B * 9) / 4;            // 9216
    const int total_q = out_size / 4;       // 12288

    const int threads = 256;
    const int blocks = (total_q + threads - 1) / threads;   // 48
    svd_identity_pose_v4<<<blocks, threads>>>(pose4, out4, r_q, total_q);
}

// round 4
// speedup vs baseline: 1.0385x; 1.0385x over previous
#include <cuda_runtime.h>

// SVD_9990093931239 — batched Kabsch alignment, algebraically collapsed.
//   tt = src + pose -> tt_c == src_c -> H = src_c @ src_c^T (symmetric PSD)
//   => U == V => R = I, det=+1 (reflection branch never taken), t = pose.
// Output: [B*9 floats of R][B*3 floats of t]. B=4096 -> 49152 floats = 192KB.
//
// R4: revert R3's hoisted load (it put a long-scoreboard wait on every warp's
// common path and regressed the ramp). Load pose ONLY on tail threads;
// R-section threads are pure ALU+STG. This kernel is launch-ramp bound:
// wall ≈ 6.85µs = graph-replay dispatch (~2.5µs) + T_ovh ramp + 192KB stores.

__global__ void svd_identity_pose_v4(const float4* __restrict__ pose4,
                                     float4* __restrict__ out4,
                                     int r_q,     // B*9/4 float4s in R section
                                     int total_q) // out_size/4
{
    int q = blockIdx.x * blockDim.x + threadIdx.x;
    if (q >= total_q) return;

    if (q < r_q) {
        // identity pattern: 1 at positions 0,4,8 of each 9-float row-major 3x3
        int p = (q * 4) % 9;
        float4 v;
        v.x = (float)((0x111u >> p) & 1u); p = (p == 8) ? 0 : p + 1;
        v.y = (float)((0x111u >> p) & 1u); p = (p == 8) ? 0 : p + 1;
        v.z = (float)((0x111u >> p) & 1u); p = (p == 8) ? 0 : p + 1;
        v.w = (float)((0x111u >> p) & 1u);
        out4[q] = v;
    } else {
        out4[q] = __ldg(&pose4[q - r_q]);   // t[b,:] = pose[b,:,0]
    }
}

extern "C" void kernel_launch(void* const* d_in, const int* in_sizes, int n_in,
                              void* d_out, int out_size)
{
    // inputs: [0]=source [B,N,3], [1]=template [B,N,3], [2]=pose [B,3,1]
    const float4* pose4 = (const float4*)d_in[2];
    float4* out4 = (float4*)d_out;

    const int B = in_sizes[2] / 3;          // 4096
    const int r_q = (B * 9) / 4;            // 9216
    const int total_q = out_size / 4;       // 12288

    const int threads = 256;
    const int blocks = (total_q + threads - 1) / threads;   // 48
    svd_identity_pose_v4<<<blocks, threads>>>(pose4, out4, r_q, total_q);
}

// round 5
// speedup vs baseline: 1.4211x; 1.3684x over previous
#include <cuda_runtime.h>

// SVD_9990093931239 — batched Kabsch alignment, algebraically collapsed.
//   tt = src + pose -> tt_c == src_c -> H = src_c @ src_c^T (symmetric PSD)
//   => U == V => R = I, det=+1 (reflection branch never taken), t = pose.
// Output: [B*9 floats of R][B*3 floats of t]. B=4096 -> 49152 floats = 192KB.
//
// R5: section-order swap. The pose-copy threads (the only ones with a
// dependent LDG) were in the LAST blocks of the grid, so their L2 latency
// extended the kernel tail. Put them FIRST: their loads issue during the
// ramp of the remaining blocks and the latency is fully overlapped.
// Identity pattern threads remain pure ALU+STG.

__global__ void svd_identity_pose_v4(const float4* __restrict__ pose4,
                                     float4* __restrict__ out4,
                                     int t_q,     // B*3/4 float4s in t section
                                     int r_q,     // B*9/4 float4s in R section
                                     int total_q) // out_size/4
{
    int q = blockIdx.x * blockDim.x + threadIdx.x;
    if (q >= total_q) return;

    if (q < t_q) {
        // pose copy first: LDG issues at the front of the ramp
        out4[r_q + q] = __ldg(&pose4[q]);          // t[b,:] = pose[b,:,0]
    } else {
        int qr = q - t_q;                          // index into R section
        int p = (qr * 4) % 9;                      // pos in 9-float 3x3 pattern
        float4 v;
        v.x = (float)((0x111u >> p) & 1u); p = (p == 8) ? 0 : p + 1;
        v.y = (float)((0x111u >> p) & 1u); p = (p == 8) ? 0 : p + 1;
        v.z = (float)((0x111u >> p) & 1u); p = (p == 8) ? 0 : p + 1;
        v.w = (float)((0x111u >> p) & 1u);
        out4[qr] = v;
    }
}

extern "C" void kernel_launch(void* const* d_in, const int* in_sizes, int n_in,
                              void* d_out, int out_size)
{
    // inputs: [0]=source [B,N,3], [1]=template [B,N,3], [2]=pose [B,3,1]
    const float4* pose4 = (const float4*)d_in[2];
    float4* out4 = (float4*)d_out;

    const int B = in_sizes[2] / 3;          // 4096
    const int t_q = (B * 3) / 4;            // 3072
    const int r_q = (B * 9) / 4;            // 9216
    const int total_q = out_size / 4;       // 12288

    const int threads = 256;
    const int blocks = (total_q + threads - 1) / threads;   // 48
    svd_identity_pose_v4<<<blocks, threads>>>(pose4, out4, t_q, r_q, total_q);
}

// round 6
// speedup vs baseline: 1.5000x; 1.0556x over previous
#include <cuda_runtime.h>

// SVD_9990093931239 — batched Kabsch alignment, algebraically collapsed.
//   tt = src + pose -> tt_c == src_c -> H = src_c @ src_c^T (symmetric PSD)
//   => U == V => R = I, det=+1 (reflection branch never taken), t = pose.
// Output: [B*9 floats of R][B*3 floats of t]. B=4096 -> 49152 floats = 192KB.
//
// R6: shrink grid 48 -> 16 blocks; each thread writes 3 coalesced float4
// slots (q, q+S, q+2S). The highest-index slot (the pose-copy/t section)
// is written FIRST so its LDG issues at the top of every thread, keeping
// R5's front-loaded-latency property; the two pure-ALU identity writes
// that follow hide the L2 latency.

__device__ __forceinline__ float4 ident_pat(int q4) {
    // q4 = float4 slot index within R section; pattern period 9 slots
    int p = (q4 * 4) % 9;        // starting float position within 3x3 row-major
    float4 v;
    v.x = (float)((0x111u >> p) & 1u); p = (p == 8) ? 0 : p + 1;
    v.y = (float)((0x111u >> p) & 1u); p = (p == 8) ? 0 : p + 1;
    v.z = (float)((0x111u >> p) & 1u); p = (p == 8) ? 0 : p + 1;
    v.w = (float)((0x111u >> p) & 1u);
    return v;
}

__global__ void svd_identity_pose_v6(const float4* __restrict__ pose4,
                                     float4* __restrict__ out4,
                                     int r_q,      // B*9/4 slots in R section
                                     int stride,   // threads total
                                     int total_q)  // out_size/4
{
    int q = blockIdx.x * blockDim.x + threadIdx.x;

    // Iteration 1 (FIRST): highest slot — contains the t section, so the
    // dependent pose LDG issues before any other work in this thread.
    int s2 = q + 2 * stride;
    if (s2 < total_q) {
        if (s2 >= r_q) out4[s2] = __ldg(&pose4[s2 - r_q]);
        else           out4[s2] = ident_pat(s2);
    }

    // Iterations 2-3: pure ALU identity-pattern writes (R section).
    int s1 = q + stride;
    if (s1 < total_q) {
        if (s1 >= r_q) out4[s1] = __ldg(&pose4[s1 - r_q]);
        else           out4[s1] = ident_pat(s1);
    }
    if (q < total_q) {
        out4[q] = ident_pat(q);   // q < stride <= r_q always in R section
    }
}

extern "C" void kernel_launch(void* const* d_in, const int* in_sizes, int n_in,
                              void* d_out, int out_size)
{
    // inputs: [0]=source [B,N,3], [1]=template [B,N,3], [2]=pose [B,3,1]
    const float4* pose4 = (const float4*)d_in[2];
    float4* out4 = (float4*)d_out;

    const int B = in_sizes[2] / 3;          // 4096
    const int r_q = (B * 9) / 4;            // 9216
    const int total_q = out_size / 4;       // 12288

    const int threads = 256;
    const int stride = (total_q + 2) / 3;   // 4096 threads cover 3 slots each
    const int blocks = (stride + threads - 1) / threads;   // 16
    svd_identity_pose_v6<<<blocks, threads>>>(pose4, out4, r_q, stride, total_q);
}